// round 12
// baseline (speedup 1.0000x reference)
#include <cuda_runtime.h>

// FeatureSim: attn[b,i,j] = softmax_j( sum_k w[k]*|x[b,i,k]-x[b,j,k]| ), mask j < len[b].
// B=8, L=1024, F=16 (first 11 used), out f32 [8,1024,1024].
//
// R12: symmetry split. s_ij == s_ji BITWISE (FADD magnitudes symmetric, same k order),
//      and the key mask depends only on the column -> unnormalized e is symmetric.
//   Pass 1: upper triangle only (50.4% of the FFMA work). Block (b,bi): rows
//           [8bi,8bi+8) x cols [8bi,1024). e[8][4] in registers; each value stored
//           twice: direct out[i][j] (float4) + mirror out[j][i] (2xSTG.128 of 8
//           contiguous row values per col). Diagonal-tile double-writes are
//           identical bits. No e-slab, no reduction, 1 barrier.
//   Pass 2: in-place. Warp-per-row: 8 masked LDG.128 -> sum -> butterfly -> rcp
//           -> scale the loaded registers -> STG. No smem, no barriers.
//      Masking & normalization live entirely in pass 2.

#define L_SEQ 1024
#define FDIM  16
#define NF    11
#define BQ    8
#define TPB   256
#define BPB   (L_SEQ / BQ)   // 128 row-tiles per batch

__device__ __forceinline__ float ex2(float a) {
    float r; asm("ex2.approx.f32 %0, %1;" : "=f"(r) : "f"(a)); return r;
}

#define LOG2E 1.4426950408889634f

// ---------------- Pass 1: symmetric e, upper triangle ----------------
__global__ __launch_bounds__(TPB, 3)
void featsim_pass1(const float* __restrict__ x,
                   const float* __restrict__ w,
                   float*       __restrict__ out)
{
    const int b     = blockIdx.x / BPB;
    const int bi    = blockIdx.x % BPB;
    const int ibase = bi * BQ;
    const int tid   = threadIdx.x;

    __shared__ __align__(16) float sq[BQ][12];   // raw queries (11 used, pad 0)

    float wl[NF];
#pragma unroll
    for (int k = 0; k < NF; ++k) wl[k] = w[k] * LOG2E;

    if (tid < BQ * 12) {
        int r = tid / 12, k = tid - r * 12;
        sq[r][k] = (k < NF) ? x[(size_t)(b * L_SEQ + ibase + r) * FDIM + k] : 0.f;
    }
    __syncthreads();

    const int j0 = ibase + tid * 4;              // this thread's 4 cols (upper region)
    if (j0 >= L_SEQ) return;

    // Keys for cols j0..j0+3.
    float kk[4][NF];
#pragma unroll
    for (int cc = 0; cc < 4; ++cc) {
        const float4* kp = reinterpret_cast<const float4*>(
            x + (size_t)(b * L_SEQ + j0 + cc) * FDIM);
        float4 a = kp[0], c = kp[1], d = kp[2];
        kk[cc][0] = a.x;  kk[cc][1] = a.y;  kk[cc][2]  = a.z;  kk[cc][3] = a.w;
        kk[cc][4] = c.x;  kk[cc][5] = c.y;  kk[cc][6]  = c.z;  kk[cc][7] = c.w;
        kk[cc][8] = d.x;  kk[cc][9] = d.y;  kk[cc][10] = d.z;
    }

    // Compute e[8][4] (raw, unmasked).
    float e[BQ][4];
#pragma unroll
    for (int r = 0; r < BQ; ++r) {
        const float4* qp = reinterpret_cast<const float4*>(sq[r]);
        float4 qa = qp[0];
        float4 qb = qp[1];
        float4 qc = qp[2];
        const float qs[NF] = { qa.x, qa.y, qa.z, qa.w,
                               qb.x, qb.y, qb.z, qb.w,
                               qc.x, qc.y, qc.z };
        float s0 = 0.f, s1 = 0.f, s2 = 0.f, s3 = 0.f;
#pragma unroll
        for (int k = 0; k < NF; ++k) {
            const float q = qs[k], wk = wl[k];
            s0 = fmaf(fabsf(q - kk[0][k]), wk, s0);
            s1 = fmaf(fabsf(q - kk[1][k]), wk, s1);
            s2 = fmaf(fabsf(q - kk[2][k]), wk, s2);
            s3 = fmaf(fabsf(q - kk[3][k]), wk, s3);
        }
        e[r][0] = ex2(s0); e[r][1] = ex2(s1); e[r][2] = ex2(s2); e[r][3] = ex2(s3);
    }

    // Direct stores: out[ibase+r][j0..j0+3].
    float* ob = out + (size_t)b * L_SEQ * L_SEQ;
#pragma unroll
    for (int r = 0; r < BQ; ++r) {
        *reinterpret_cast<float4*>(ob + (size_t)(ibase + r) * L_SEQ + j0) =
            make_float4(e[r][0], e[r][1], e[r][2], e[r][3]);
    }

    // Mirror stores: out[j0+cc][ibase..ibase+8) = e[0..7][cc] (8 contiguous floats).
#pragma unroll
    for (int cc = 0; cc < 4; ++cc) {
        float* mp = ob + (size_t)(j0 + cc) * L_SEQ + ibase;
        *reinterpret_cast<float4*>(mp)     = make_float4(e[0][cc], e[1][cc], e[2][cc], e[3][cc]);
        *reinterpret_cast<float4*>(mp + 4) = make_float4(e[4][cc], e[5][cc], e[6][cc], e[7][cc]);
    }
}

// ---------------- Pass 2: mask + row-softmax normalize, in place ----------------
__global__ __launch_bounds__(TPB)
void featsim_pass2(const int* __restrict__ lens,
                   float*     __restrict__ out)
{
    const int b    = blockIdx.x / BPB;
    const int rblk = blockIdx.x % BPB;
    const int lane = threadIdx.x & 31;
    const int warp = threadIdx.x >> 5;           // warp owns one row
    const int row  = rblk * BQ + warp;
    const int len  = lens[b];

    float* rp = out + (size_t)(b * L_SEQ + row) * L_SEQ;

    float4 v[8];
    float acc = 0.f;
#pragma unroll
    for (int p = 0; p < 8; ++p) {
        const int c0 = lane * 4 + p * 128;
        float4 t = *reinterpret_cast<const float4*>(rp + c0);
        t.x = (c0 + 0 < len) ? t.x : 0.f;
        t.y = (c0 + 1 < len) ? t.y : 0.f;
        t.z = (c0 + 2 < len) ? t.z : 0.f;
        t.w = (c0 + 3 < len) ? t.w : 0.f;
        v[p] = t;
        acc += (t.x + t.y) + (t.z + t.w);
    }
#pragma unroll
    for (int o = 16; o > 0; o >>= 1)
        acc += __shfl_xor_sync(0xffffffffu, acc, o);

    float inv; asm("rcp.approx.f32 %0, %1;" : "=f"(inv) : "f"(acc));   // len>=1 => acc>0

#pragma unroll
    for (int p = 0; p < 8; ++p) {
        const int c0 = lane * 4 + p * 128;
        *reinterpret_cast<float4*>(rp + c0) =
            make_float4(v[p].x * inv, v[p].y * inv, v[p].z * inv, v[p].w * inv);
    }
}

extern "C" void kernel_launch(void* const* d_in, const int* in_sizes, int n_in,
                              void* d_out, int out_size)
{
    const float* x    = (const float*)d_in[0];   // [8,1024,16] f32
    const int*   lens = (const int*)d_in[1];     // [8] i32
    const float* w    = (const float*)d_in[2];   // [11] f32
    float*       out  = (float*)d_out;           // [8,1024,1024] f32

    dim3 grid(8 * BPB);    // 1024 blocks each pass
    dim3 block(TPB);
    featsim_pass1<<<grid, block>>>(x, w, out);
    featsim_pass2<<<grid, block>>>(lens, out);
}

// round 13
// speedup vs baseline: 1.5143x; 1.5143x over previous
#include <cuda_runtime.h>

// FeatureSim: attn[b,i,j] = softmax_j( sum_k w[k]*|x[b,i,k]-x[b,j,k]| ), mask j < len[b].
// B=8, L=1024, F=16 (first 11 used), out f32 [8,1024,1024].
//
// R13: R10 (best) + STRIDED column ownership. Duration tracks L1 wavefronts;
//      R10's key loads (4 consecutive rows/thread -> 256B lane stride) splinter
//      each LDG.128 into ~32 wavefronts (3072/block ~= 40% of all wavefronts).
//      Thread now owns cols {t, t+256, t+512, t+768}: key-load lane stride 64B,
//      2 lanes per 128B line -> 16 wavefronts/inst, halving the key-load cost.
//      Slab/output writes become 4 scalar ops (same wavefront count; lanes are
//      consecutive -> conflict-free STS.32 / fully-coalesced STG.32).
//      Everything else identical to R10: scalar FADD/FFMA core (free |.|/-),
//      ex2.approx, mask as -1e30 bias, e-slab once, fused warp-per-row epilogue,
//      2 barriers, 3 blocks/SM.

#define L_SEQ 1024
#define FDIM  16
#define NF    11
#define BQ    8             // rows per block == warps per block
#define TPB   256
#define BPB   (L_SEQ / BQ)  // 128 blocks per batch
#define CSTRIDE (L_SEQ / 4) // 256: column stride between a thread's 4 cols

__device__ __forceinline__ float ex2(float a) {
    float r; asm("ex2.approx.f32 %0, %1;" : "=f"(r) : "f"(a)); return r;
}

#define LOG2E 1.4426950408889634f

__global__ __launch_bounds__(TPB, 3)
void featsim_kernel(const float* __restrict__ x,
                    const int*   __restrict__ lens,
                    const float* __restrict__ w,
                    float*       __restrict__ out)
{
    const int b    = blockIdx.x / BPB;
    const int rb   = blockIdx.x % BPB;
    const int i0   = rb * BQ;
    const int tid  = threadIdx.x;
    const int lane = tid & 31;
    const int warp = tid >> 5;          // 0..7; warp w owns row w in the epilogue

    __shared__ __align__(16) float sq[BQ][12];      // raw queries (11 used, pad 0)
    __shared__ __align__(16) float se[BQ][L_SEQ];   // unnormalized e staging (32 KB)

    // Signed per-feature scale wl_k = w_k * log2e (|d| via free abs modifier).
    float wl[NF];
#pragma unroll
    for (int k = 0; k < NF; ++k) wl[k] = w[k] * LOG2E;

    // Stage raw queries.
    if (tid < BQ * 12) {
        int r = tid / 12, k = tid - r * 12;
        sq[r][k] = (k < NF) ? x[(size_t)(b * L_SEQ + i0 + r) * FDIM + k] : 0.f;
    }

    // Keys: 4 STRIDED cols (tid + 256*cc). Lane stride between key rows = 64B,
    // so each LDG.128 needs only ~16 L1 wavefronts (2 lanes share a 128B line).
    float kk[4][NF];
#pragma unroll
    for (int cc = 0; cc < 4; ++cc) {
        const float4* kp = reinterpret_cast<const float4*>(
            x + (size_t)(b * L_SEQ + tid + CSTRIDE * cc) * FDIM);
        float4 a = kp[0], c = kp[1], d = kp[2];
        kk[cc][0] = a.x;  kk[cc][1] = a.y;  kk[cc][2]  = a.z;  kk[cc][3] = a.w;
        kk[cc][4] = c.x;  kk[cc][5] = c.y;  kk[cc][6]  = c.z;  kk[cc][7] = c.w;
        kk[cc][8] = d.x;  kk[cc][9] = d.y;  kk[cc][10] = d.z;
    }

    // Key-mask as accumulator bias: invalid col -> -1e30 -> ex2 -> exact 0.
    const int len = lens[b];
    float bias[4];
#pragma unroll
    for (int cc = 0; cc < 4; ++cc)
        bias[cc] = (tid + CSTRIDE * cc < len) ? 0.f : -1e30f;

    __syncthreads();

    // ---- compute: 3 LDS.128/row + 88 FADD/FFMA + 4 ex2 + 4 STS.32 ----
#pragma unroll
    for (int r = 0; r < BQ; ++r) {
        const float4* qp = reinterpret_cast<const float4*>(sq[r]);
        float4 qa = qp[0];              // features 0..3
        float4 qb = qp[1];              // features 4..7
        float4 qc = qp[2];              // features 8..10 (+pad)
        const float qs[NF] = { qa.x, qa.y, qa.z, qa.w,
                               qb.x, qb.y, qb.z, qb.w,
                               qc.x, qc.y, qc.z };

        float s0 = bias[0], s1 = bias[1], s2 = bias[2], s3 = bias[3];
#pragma unroll
        for (int k = 0; k < NF; ++k) {
            const float q = qs[k], wk = wl[k];
            s0 = fmaf(fabsf(q - kk[0][k]), wk, s0);
            s1 = fmaf(fabsf(q - kk[1][k]), wk, s1);
            s2 = fmaf(fabsf(q - kk[2][k]), wk, s2);
            s3 = fmaf(fabsf(q - kk[3][k]), wk, s3);
        }

        // 4 scalar STS, lanes consecutive -> conflict-free, 1 wavefront each.
        se[r][tid + 0 * CSTRIDE] = ex2(s0);
        se[r][tid + 1 * CSTRIDE] = ex2(s1);
        se[r][tid + 2 * CSTRIDE] = ex2(s2);
        se[r][tid + 3 * CSTRIDE] = ex2(s3);
    }
    __syncthreads();

    // ---- fused reduce + normalize + store: warp w owns row w ----
    {
        float4 v[8];
        float acc = 0.f;
#pragma unroll
        for (int p = 0; p < 8; ++p) {
            v[p] = *reinterpret_cast<float4*>(&se[warp][lane * 4 + p * 128]);
            acc += (v[p].x + v[p].y) + (v[p].z + v[p].w);
        }
#pragma unroll
        for (int o = 16; o > 0; o >>= 1)
            acc += __shfl_xor_sync(0xffffffffu, acc, o);

        float inv; asm("rcp.approx.f32 %0, %1;" : "=f"(inv) : "f"(acc));  // len>=1 => acc>0

        float4* orow = reinterpret_cast<float4*>(
            out + (size_t)(b * L_SEQ + i0 + warp) * L_SEQ);
#pragma unroll
        for (int p = 0; p < 8; ++p) {
            orow[p * 32 + lane] =
                make_float4(v[p].x * inv, v[p].y * inv, v[p].z * inv, v[p].w * inv);
        }
    }
}

extern "C" void kernel_launch(void* const* d_in, const int* in_sizes, int n_in,
                              void* d_out, int out_size)
{
    const float* x    = (const float*)d_in[0];   // [8,1024,16] f32
    const int*   lens = (const int*)d_in[1];     // [8] i32
    const float* w    = (const float*)d_in[2];   // [11] f32
    float*       out  = (float*)d_out;           // [8,1024,1024] f32

    dim3 grid(8 * BPB);   // 1024 blocks
    dim3 block(TPB);
    featsim_kernel<<<grid, block>>>(x, lens, w, out);
}